// round 15
// baseline (speedup 1.0000x reference)
#include <cuda_runtime.h>
#include <cuda_bf16.h>

#define NBLOCKS 2048
#define MAX_ROWS (1 << 20)   // supports up to 1M rows (bench: 524288)

// Scratch (no device allocs allowed).
__device__ float    g_pos[MAX_ROWS];   // gathered positive score per row (4 MB static)
__device__ double   g_part[NBLOCKS];
__device__ unsigned g_ticket;          // zero-init; reset by the closing block each call

// ---------------- Pass 1: gather pos[r] = x[r*128 + target[r]] ----------------
__global__ void __launch_bounds__(256) mrl_gather_kernel(
    const float* __restrict__ x,
    const void* __restrict__ target,
    int rows)
{
    const int lane = threadIdx.x & 31;

    // Per-warp dtype probe: int64 targets in [0,128) have all-zero odd 32-bit
    // words in the first 256 words; int32 targets make that impossible.
    const int* t32p = (const int*)target;
    int nz = 0;
    #pragma unroll
    for (int j = 0; j < 4; j++)
        nz |= __ldg(t32p + 1 + 2 * (lane * 4 + j));
    const bool is64 = (__ballot_sync(0xFFFFFFFFu, nz != 0) == 0u);

    const int*       t32 = (const int*)target;
    const long long* t64 = (const long long*)target;

    const int gtid = blockIdx.x * blockDim.x + threadIdx.x;
    const int nthr = gridDim.x * blockDim.x;

    if (is64) {
        for (int r = gtid; r < rows; r += nthr)
            g_pos[r] = __ldg(x + (size_t)r * 128 + (int)t64[r]);
    } else {
        for (int r = gtid; r < rows; r += nthr)
            g_pos[r] = __ldg(x + (size_t)r * 128 + t32[r]);
    }
}

// ---------------- Pass 2: pure stream over x + linear pos reads ----------------
// Warp per 4 rows, grid-stride. Loop body has ZERO dependent / gather loads:
// 1 coalesced float4 of pos + 4 LDG.128 of x.
__global__ void __launch_bounds__(256) mrl_stream_kernel(
    const float* __restrict__ x,
    int rows, double inv_cnt,
    float* __restrict__ out)
{
    const int tid    = threadIdx.x;
    const int lane   = tid & 31;
    const int wid    = tid >> 5;
    const int gwarp  = (blockIdx.x * blockDim.x + tid) >> 5;
    const int nwarps = (gridDim.x * blockDim.x) >> 5;

    float a0 = 0.f, a1 = 0.f, a2 = 0.f, a3 = 0.f;

    int r = gwarp * 4;
    const int stride = nwarps * 4;

    for (; r + 3 < rows; r += stride) {
        // Linear-address loads only; all independent.
        const float4 pq = *reinterpret_cast<const float4*>(g_pos + r);
        const float* p = x + (size_t)r * 128;
        const float4 v0 = reinterpret_cast<const float4*>(p        )[lane];
        const float4 v1 = reinterpret_cast<const float4*>(p + 128  )[lane];
        const float4 v2 = reinterpret_cast<const float4*>(p + 256  )[lane];
        const float4 v3 = reinterpret_cast<const float4*>(p + 384  )[lane];

        const float b0 = 0.5f - pq.x;
        const float b1 = 0.5f - pq.y;
        const float b2 = 0.5f - pq.z;
        const float b3 = 0.5f - pq.w;

        a0 += fmaxf(v0.x + b0, 0.f) + fmaxf(v0.y + b0, 0.f)
            + fmaxf(v0.z + b0, 0.f) + fmaxf(v0.w + b0, 0.f);
        a1 += fmaxf(v1.x + b1, 0.f) + fmaxf(v1.y + b1, 0.f)
            + fmaxf(v1.z + b1, 0.f) + fmaxf(v1.w + b1, 0.f);
        a2 += fmaxf(v2.x + b2, 0.f) + fmaxf(v2.y + b2, 0.f)
            + fmaxf(v2.z + b2, 0.f) + fmaxf(v2.w + b2, 0.f);
        a3 += fmaxf(v3.x + b3, 0.f) + fmaxf(v3.y + b3, 0.f)
            + fmaxf(v3.z + b3, 0.f) + fmaxf(v3.w + b3, 0.f);
    }

    // Tail (none for the benchmark shape; kept for generality).
    for (; r < rows; r++) {
        const float* p = x + (size_t)r * 128;
        const float4 v = reinterpret_cast<const float4*>(p)[lane];
        const float b  = 0.5f - g_pos[r];
        a0 += fmaxf(v.x + b, 0.f) + fmaxf(v.y + b, 0.f)
            + fmaxf(v.z + b, 0.f) + fmaxf(v.w + b, 0.f);
    }

    // Lane partials -> warp -> block.
    double d = (double)a0 + (double)a1 + (double)a2 + (double)a3;
    #pragma unroll
    for (int o = 16; o > 0; o >>= 1)
        d += __shfl_xor_sync(0xFFFFFFFFu, d, o);

    __shared__ double ws[8];
    if (lane == 0) ws[wid] = d;
    __syncthreads();

    __shared__ bool s_last;
    if (tid == 0) {
        double b = 0.0;
        #pragma unroll
        for (int i = 0; i < 8; i++) b += ws[i];
        g_part[blockIdx.x] = b;
        __threadfence();
        unsigned t = atomicAdd(&g_ticket, 1u);
        s_last = (t == (unsigned)gridDim.x - 1u);
    }
    __syncthreads();

    // ---- closing block: reduce all partials, finish, reset ticket ----
    if (s_last) {
        double s = 0.0;
        for (int i = tid; i < NBLOCKS; i += 256) s += g_part[i];
        #pragma unroll
        for (int o = 16; o > 0; o >>= 1)
            s += __shfl_xor_sync(0xFFFFFFFFu, s, o);
        if (lane == 0) ws[wid] = s;
        __syncthreads();
        if (tid == 0) {
            double b = 0.0;
            #pragma unroll
            for (int i = 0; i < 8; i++) b += ws[i];
            // Each row's target position contributed exactly max(0, 0.5) = 0.5.
            out[0] = (float)((b - 0.5 * (double)rows) * inv_cnt);
            g_ticket = 0;   // reset for the next (graph-replayed) call
        }
    }
}

extern "C" void kernel_launch(void* const* d_in, const int* in_sizes, int n_in,
                              void* d_out, int out_size)
{
    const float* x      = (const float*)d_in[0];   // [V, C, T] fp32
    const void*  target = d_in[1];                 // [V, C] int32 or int64 (auto-detected)
    float*       out    = (float*)d_out;

    const int T    = 128;
    const int rows = in_sizes[0] / T;              // V*C
    const double cnt = (double)rows * (double)(T - 1);

    mrl_gather_kernel<<<1024, 256>>>(x, target, rows);
    mrl_stream_kernel<<<NBLOCKS, 256>>>(x, rows, 1.0 / cnt, out);
}

// round 16
// speedup vs baseline: 1.1429x; 1.1429x over previous
#include <cuda_runtime.h>
#include <cuda_bf16.h>
#include <cstdint>

#define NBLOCKS        2048
#define THREADS        256
#define ROWS_PER_CHUNK 16
#define CHUNK_FLOATS   (ROWS_PER_CHUNK * 128)   // 2048 floats
#define CHUNK_BYTES    (CHUNK_FLOATS * 4)       // 8192 B
#define NSTAGES        4

// Scratch (no device allocs allowed).
__device__ double   g_part[NBLOCKS];
__device__ unsigned g_ticket;   // zero-init; reset to 0 by the closing block each call

__device__ __forceinline__ uint32_t smem_u32(const void* p) {
    return (uint32_t)__cvta_generic_to_shared(p);
}

__device__ __forceinline__ void mbar_init(uint32_t a, uint32_t cnt) {
    asm volatile("mbarrier.init.shared.b64 [%0], %1;" :: "r"(a), "r"(cnt) : "memory");
}
__device__ __forceinline__ void mbar_expect_tx(uint32_t a, uint32_t bytes) {
    asm volatile("mbarrier.arrive.expect_tx.shared.b64 _, [%0], %1;" :: "r"(a), "r"(bytes) : "memory");
}
__device__ __forceinline__ void mbar_wait(uint32_t a, uint32_t parity) {
    asm volatile(
        "{\n\t"
        ".reg .pred P1;\n\t"
        "WAIT_LOOP_%=:\n\t"
        "mbarrier.try_wait.parity.acquire.cta.shared::cta.b64 P1, [%0], %1, 0x989680;\n\t"
        "@P1 bra.uni WAIT_DONE_%=;\n\t"
        "bra.uni WAIT_LOOP_%=;\n\t"
        "WAIT_DONE_%=:\n\t"
        "}"
        :: "r"(a), "r"(parity) : "memory");
}
__device__ __forceinline__ void bulk_copy(uint32_t dst_smem, const void* src, uint32_t bytes, uint32_t mbar) {
    asm volatile(
        "cp.async.bulk.shared::cta.global.mbarrier::complete_tx::bytes [%0], [%1], %2, [%3];"
        :: "r"(dst_smem), "l"(src), "r"(bytes), "r"(mbar) : "memory");
}

// x: [rows, 128] fp32, streamed HBM->SMEM via cp.async.bulk (TMA path),
// computed from SMEM. pos gather becomes a broadcast LDS.
__global__ void __launch_bounds__(THREADS) mrl_bulk_kernel(
    const float* __restrict__ x,
    const void* __restrict__ target,
    int rows, double inv_cnt,
    float* __restrict__ out)
{
    __shared__ __align__(128) float s_buf[NSTAGES][CHUNK_FLOATS];   // 32 KB
    __shared__ __align__(8) unsigned long long s_mbar[NSTAGES];
    __shared__ double ws[8];
    __shared__ bool   s_last;

    const int tid  = threadIdx.x;
    const int lane = tid & 31;
    const int wid  = tid >> 5;

    // ---- per-warp dtype probe: int64 targets in [0,128) have all-zero odd
    // 32-bit words in the first 256 words; int32 targets make that impossible.
    const int* t32p = (const int*)target;
    int nz = 0;
    #pragma unroll
    for (int j = 0; j < 4; j++)
        nz |= __ldg(t32p + 1 + 2 * (lane * 4 + j));
    const bool is64 = (__ballot_sync(0xFFFFFFFFu, nz != 0) == 0u);

    const int*       t32 = (const int*)target;
    const long long* t64 = (const long long*)target;

    // ---- pipeline setup ----
    const int rows_main = rows & ~(ROWS_PER_CHUNK - 1);
    const int nchunks   = rows_main / ROWS_PER_CHUNK;
    const int G         = gridDim.x;
    const int c0        = blockIdx.x;
    const int myn       = (c0 < nchunks) ? ((nchunks - c0 + G - 1) / G) : 0;

    uint32_t mb[NSTAGES];
    #pragma unroll
    for (int s = 0; s < NSTAGES; s++) mb[s] = smem_u32(&s_mbar[s]);

    if (tid == 0) {
        #pragma unroll
        for (int s = 0; s < NSTAGES; s++) mbar_init(mb[s], 1);
    }
    __syncthreads();

    if (tid == 0) {
        const int pre = (myn < NSTAGES) ? myn : NSTAGES;
        for (int s = 0; s < pre; s++) {
            const int chunk = c0 + s * G;
            mbar_expect_tx(mb[s], CHUNK_BYTES);
            bulk_copy(smem_u32(&s_buf[s][0]), x + (size_t)chunk * CHUNK_FLOATS,
                      CHUNK_BYTES, mb[s]);
        }
    }

    float a0 = 0.f, a1 = 0.f, a2 = 0.f, a3 = 0.f;

    for (int i = 0; i < myn; i++) {
        const int s      = i & (NSTAGES - 1);
        const int parity = (i >> 2) & 1;
        const int chunk  = c0 + i * G;
        const int ra     = chunk * ROWS_PER_CHUNK + wid * 2;   // this warp's 2 rows

        // Prefetch targets BEFORE the barrier wait (independent of stage data).
        int ta, tb;
        if (is64) {
            const longlong2 tt = *reinterpret_cast<const longlong2*>(t64 + ra);
            ta = (int)tt.x; tb = (int)tt.y;
        } else {
            const int2 tt = *reinterpret_cast<const int2*>(t32 + ra);
            ta = tt.x; tb = tt.y;
        }

        mbar_wait(mb[s], (uint32_t)parity);

        const float* sb = &s_buf[s][0];
        const float* pa = sb + (wid * 2    ) * 128;
        const float* pb = sb + (wid * 2 + 1) * 128;
        const float4 va = reinterpret_cast<const float4*>(pa)[lane];
        const float4 vb = reinterpret_cast<const float4*>(pb)[lane];
        const float  ba = 0.5f - pa[ta];   // broadcast LDS (free gather)
        const float  bb = 0.5f - pb[tb];

        a0 += fmaxf(va.x + ba, 0.f) + fmaxf(va.y + ba, 0.f);
        a1 += fmaxf(va.z + ba, 0.f) + fmaxf(va.w + ba, 0.f);
        a2 += fmaxf(vb.x + bb, 0.f) + fmaxf(vb.y + bb, 0.f);
        a3 += fmaxf(vb.z + bb, 0.f) + fmaxf(vb.w + bb, 0.f);

        __syncthreads();   // all warps done reading stage s

        if (tid == 0 && i + NSTAGES < myn) {
            const int nc = c0 + (i + NSTAGES) * G;
            mbar_expect_tx(mb[s], CHUNK_BYTES);
            bulk_copy(smem_u32(&s_buf[s][0]), x + (size_t)nc * CHUNK_FLOATS,
                      CHUNK_BYTES, mb[s]);
        }
    }

    // ---- tail rows (rows % 16, none for bench shape): block 0, global path ----
    if (blockIdx.x == 0) {
        for (int r = rows_main + wid; r < rows; r += 8) {
            const int tgt = is64 ? (int)t64[r] : t32[r];
            const float* p = x + (size_t)r * 128;
            const float4 v = reinterpret_cast<const float4*>(p)[lane];
            const float b  = 0.5f - __ldg(p + tgt);
            a0 += fmaxf(v.x + b, 0.f) + fmaxf(v.y + b, 0.f)
                + fmaxf(v.z + b, 0.f) + fmaxf(v.w + b, 0.f);
        }
    }

    // ---- lane partials -> warp -> block ----
    double d = (double)a0 + (double)a1 + (double)a2 + (double)a3;
    #pragma unroll
    for (int o = 16; o > 0; o >>= 1)
        d += __shfl_xor_sync(0xFFFFFFFFu, d, o);

    if (lane == 0) ws[wid] = d;
    __syncthreads();

    if (tid == 0) {
        double b = 0.0;
        #pragma unroll
        for (int i = 0; i < 8; i++) b += ws[i];
        g_part[blockIdx.x] = b;
        __threadfence();
        unsigned t = atomicAdd(&g_ticket, 1u);
        s_last = (t == (unsigned)gridDim.x - 1u);
    }
    __syncthreads();

    // ---- closing block: reduce all partials, finish, reset ticket ----
    if (s_last) {
        double s = 0.0;
        for (int i = tid; i < NBLOCKS; i += THREADS) s += g_part[i];
        #pragma unroll
        for (int o = 16; o > 0; o >>= 1)
            s += __shfl_xor_sync(0xFFFFFFFFu, s, o);
        if (lane == 0) ws[wid] = s;
        __syncthreads();
        if (tid == 0) {
            double b = 0.0;
            #pragma unroll
            for (int i = 0; i < 8; i++) b += ws[i];
            // Each row's target position contributed exactly max(0, 0.5) = 0.5.
            out[0] = (float)((b - 0.5 * (double)rows) * inv_cnt);
            g_ticket = 0;   // reset for the next (graph-replayed) call
        }
    }
}

extern "C" void kernel_launch(void* const* d_in, const int* in_sizes, int n_in,
                              void* d_out, int out_size)
{
    const float* x      = (const float*)d_in[0];   // [V, C, T] fp32
    const void*  target = d_in[1];                 // [V, C] int32 or int64 (auto-detected)
    float*       out    = (float*)d_out;

    const int T    = 128;
    const int rows = in_sizes[0] / T;              // V*C
    const double cnt = (double)rows * (double)(T - 1);

    mrl_bulk_kernel<<<NBLOCKS, THREADS>>>(x, target, rows, 1.0 / cnt, out);
}